// round 11
// baseline (speedup 1.0000x reference)
#include <cuda_runtime.h>
#include <math.h>

#define T_STEPS 512
#define B_SZ    64
#define HID     512
#define G3      1536
#define M_ROWS  (T_STEPS * B_SZ)          // 32768
#define OUT_TB  (T_STEPS * B_SZ * 1024)   // 33554432 floats

// ---------------- device scratch (static: no allocations allowed) ----------------
__device__ float    g_gi[2L * M_ROWS * G3];         // [dir][t*B+b][1536]
__device__ float    g_h[2 * 2 * B_SZ * HID];        // [dir][parity][b][h]
__device__ unsigned g_bar;

static __device__ __forceinline__ unsigned ld_acq(const unsigned* p) {
    unsigned v;
    asm volatile("ld.acquire.gpu.u32 %0, [%1];" : "=r"(v) : "l"(p));
    return v;
}

// =====================================================================
// Kernel A: gi[dir][m][n] = inp[m][:] . Wih[n][:] + bih[n]
// M=32768, N=1536, K=512.  BM=BN=64, BK=16, 128 threads, 4x8 thread tile.
// =====================================================================
#define ASTR 68
__global__ void __launch_bounds__(128) gemm_in(
    const float* __restrict__ inp, const float* __restrict__ Wih,
    const float* __restrict__ bih, int dir)
{
    __shared__ float As[16 * ASTR];
    __shared__ float Bs[16 * ASTR];
    const int t  = threadIdx.x;
    const int m0 = blockIdx.y * 64;
    const int n0 = blockIdx.x * 64;
    const float* Ap = inp + (size_t)m0 * 512;
    const float* Bp = Wih + (size_t)n0 * 512;
    const int lr = t >> 2;        // 0..31
    const int lv = t & 3;         // float4 index within 16-k panel
    const int tm = t & 15;        // 16 m-groups of 4
    const int tn = t >> 4;        // 8 n-groups of 8

    float acc[4][8];
#pragma unroll
    for (int i = 0; i < 4; i++)
#pragma unroll
        for (int j = 0; j < 8; j++) acc[i][j] = 0.f;

    for (int k0 = 0; k0 < 512; k0 += 16) {
#pragma unroll
        for (int ps = 0; ps < 2; ps++) {
            int r = lr + ps * 32;
            float4 av = *(const float4*)(Ap + (size_t)r * 512 + k0 + lv * 4);
            float4 wv = *(const float4*)(Bp + (size_t)r * 512 + k0 + lv * 4);
            int kb = lv * 4;
            As[(kb + 0) * ASTR + r] = av.x;  As[(kb + 1) * ASTR + r] = av.y;
            As[(kb + 2) * ASTR + r] = av.z;  As[(kb + 3) * ASTR + r] = av.w;
            Bs[(kb + 0) * ASTR + r] = wv.x;  Bs[(kb + 1) * ASTR + r] = wv.y;
            Bs[(kb + 2) * ASTR + r] = wv.z;  Bs[(kb + 3) * ASTR + r] = wv.w;
        }
        __syncthreads();
#pragma unroll
        for (int kk = 0; kk < 16; kk++) {
            float4 a  = *(const float4*)&As[kk * ASTR + tm * 4];
            float4 w0 = *(const float4*)&Bs[kk * ASTR + tn * 8];
            float4 w1 = *(const float4*)&Bs[kk * ASTR + tn * 8 + 4];
            const float aa[4] = {a.x, a.y, a.z, a.w};
            const float ww[8] = {w0.x, w0.y, w0.z, w0.w, w1.x, w1.y, w1.z, w1.w};
#pragma unroll
            for (int i = 0; i < 4; i++)
#pragma unroll
                for (int j = 0; j < 8; j++) acc[i][j] += aa[i] * ww[j];
        }
        __syncthreads();
    }

    float bj[8];
#pragma unroll
    for (int j = 0; j < 8; j++) bj[j] = bih[n0 + tn * 8 + j];
    float* op = g_gi + (size_t)dir * M_ROWS * G3;
#pragma unroll
    for (int i = 0; i < 4; i++) {
        size_t row = (size_t)(m0 + tm * 4 + i) * G3 + n0 + tn * 8;
        float4 v0 = make_float4(acc[i][0] + bj[0], acc[i][1] + bj[1],
                                acc[i][2] + bj[2], acc[i][3] + bj[3]);
        float4 v1 = make_float4(acc[i][4] + bj[4], acc[i][5] + bj[5],
                                acc[i][6] + bj[6], acc[i][7] + bj[7]);
        *(float4*)(op + row)     = v0;
        *(float4*)(op + row + 4) = v1;
    }
}

// =====================================================================
// Init: reset barrier, load h0 into parity-0 h buffers.
// =====================================================================
__global__ void init_k(const float* __restrict__ h0f, const float* __restrict__ h0b)
{
    int i = blockIdx.x * blockDim.x + threadIdx.x;
    if (i == 0) g_bar = 0u;
    if (i < B_SZ * HID) {
        g_h[i]         = h0f[i];   // dir0, parity0
        g_h[65536 + i] = h0b[i];   // dir1, parity0
    }
}

// =====================================================================
// Kernel B: persistent bidirectional GRU recurrence.
// 128 blocks: dir = bx/64, each owns 8 h-cols (24 gate rows of Whh in smem,
// loaded once, reused for all 512 steps).
// 192 threads: two k-halves of 96 (16 b-groups x 6 c-groups, 4x4 tiles).
// One grid barrier per step (monotonic counter; all 128 blocks resident:
// 104448 B dyn smem -> 1 block/SM, 128 <= 148 SMs).
// smem: ws 512x28 | hs 128x68 | ghs 2x(24x64)
// =====================================================================
#define WSN   (512 * 28)
#define HSN   (128 * 68)
#define GHN   1536
#define SMEMB ((WSN + HSN + 2 * GHN) * 4)

__global__ void __launch_bounds__(192) gru_rec(
    const float* __restrict__ Whh_f, const float* __restrict__ Whh_b,
    const float* __restrict__ bhh_f, const float* __restrict__ bhh_b,
    float* __restrict__ out)
{
    extern __shared__ float sm[];
    float* ws  = sm;            // [k 0..511][c 0..27]
    float* hs  = ws + WSN;      // [krow 0..127][b 0..63] stride 68
    float* ghs = hs + HSN;      // two halves of [c 0..23][b 0..63]

    const int bx  = blockIdx.x;
    const int dir = bx >> 6;
    const int j0  = (bx & 63) * 8;
    const int tid = threadIdx.x;
    const int half = tid / 96;
    const int htid = tid % 96;
    const int bg = htid & 15;         // b-group (4 rows)
    const int cg = htid / 16;         // c-group (4 cols), 0..5
    const int kbase = half * 256;

    const float* Whh = dir ? Whh_b : Whh_f;
    const float* bhh = dir ? bhh_b : bhh_f;

    // Load this block's 24 Whh rows into smem [k][c], once.
    for (int idx = tid; idx < 24 * 512; idx += 192) {
        int c = idx >> 9, k = idx & 511;
        int gr = (c >> 3) * 512 + j0 + (c & 7);
        ws[k * 28 + c] = Whh[(size_t)gr * 512 + k];
    }
    // Per-thread gate biases for this block's 8 columns (hoisted).
    float br[8], bz[8], bn[8];
#pragma unroll
    for (int jj = 0; jj < 8; jj++) {
        br[jj] = bhh[j0 + jj];
        bz[jj] = bhh[512 + j0 + jj];
        bn[jj] = bhh[1024 + j0 + jj];
    }
    __syncthreads();

    for (int s = 0; s < T_STEPS; s++) {
        const int par = s & 1;
        const float* hp = g_h + ((size_t)dir * 2 + par) * (B_SZ * HID);
        float* hw = g_h + ((size_t)dir * 2 + (1 - par)) * (B_SZ * HID);

        float acc[4][4];
#pragma unroll
        for (int i = 0; i < 4; i++)
#pragma unroll
            for (int j = 0; j < 4; j++) acc[i][j] = 0.f;

        for (int p = 0; p < 4; p++) {
            // Stage 128 k-rows of h (64 per half) transposed into hs.
#pragma unroll
            for (int q = 0; q < 11; q++) {
                int v = tid + q * 192;
                if (v < 2048) {
                    int b = v >> 5, kv = v & 31;
                    int hv4 = kv >> 4;                    // which half's panel
                    int kglob = hv4 * 256 + p * 64 + ((kv * 4) & 63);
                    float4 x = *(const float4*)(hp + (size_t)b * 512 + kglob);
                    int ib = kv * 4;
                    hs[(ib + 0) * 68 + b] = x.x;  hs[(ib + 1) * 68 + b] = x.y;
                    hs[(ib + 2) * 68 + b] = x.z;  hs[(ib + 3) * 68 + b] = x.w;
                }
            }
            __syncthreads();
#pragma unroll 8
            for (int kk = 0; kk < 64; kk++) {
                float4 h4 = *(const float4*)&hs[(half * 64 + kk) * 68 + bg * 4];
                float4 w4 = *(const float4*)&ws[(kbase + p * 64 + kk) * 28 + cg * 4];
                const float hh[4] = {h4.x, h4.y, h4.z, h4.w};
                const float wc[4] = {w4.x, w4.y, w4.z, w4.w};
#pragma unroll
                for (int i = 0; i < 4; i++)
#pragma unroll
                    for (int j = 0; j < 4; j++) acc[i][j] += hh[i] * wc[j];
            }
            __syncthreads();
        }

        // Store partial gh for this half.
        float* ghp = ghs + half * GHN;
#pragma unroll
        for (int j = 0; j < 4; j++)
#pragma unroll
            for (int i = 0; i < 4; i++)
                ghp[(cg * 4 + j) * 64 + bg * 4 + i] = acc[i][j];
        __syncthreads();

        // Gate math for this block's 8 h-columns.
        const int tg = dir ? (511 - s) : s;
        const float* gip = g_gi + ((size_t)dir * T_STEPS + tg) * (B_SZ * G3);
#pragma unroll
        for (int q = 0; q < 3; q++) {
            int idx = tid + q * 192;
            if (idx < 512) {
                int b = idx >> 3, jj = idx & 7;
                int j = j0 + jj;
                float gr = ghs[jj * 64 + b]        + ghs[GHN + jj * 64 + b]        + br[jj];
                float gz = ghs[(8 + jj) * 64 + b]  + ghs[GHN + (8 + jj) * 64 + b]  + bz[jj];
                float gn = ghs[(16 + jj) * 64 + b] + ghs[GHN + (16 + jj) * 64 + b] + bn[jj];
                size_t gb = (size_t)b * G3;
                float ir = gip[gb + j], iz = gip[gb + 512 + j], in_ = gip[gb + 1024 + j];
                float r = 1.f / (1.f + __expf(-(ir + gr)));
                float z = 1.f / (1.f + __expf(-(iz + gz)));
                float n = tanhf(in_ + r * gn);
                float hn = (1.f - z) * n + z * hp[(size_t)b * 512 + j];
                hw[(size_t)b * 512 + j] = hn;
                out[(size_t)tg * 65536 + (size_t)b * 1024 + dir * 512 + j] = hn;
                if (s == 511)
                    out[(size_t)OUT_TB + dir * 32768 + b * 512 + j] = hn;
            }
        }

        // Grid barrier (monotonic counter; all 128 blocks are resident).
        __threadfence();
        __syncthreads();
        if (tid == 0) {
            atomicAdd(&g_bar, 1u);
            unsigned target = (unsigned)(s + 1) * 128u;
            while (ld_acq(&g_bar) < target) __nanosleep(64);
        }
        __syncthreads();
    }
}

// =====================================================================
extern "C" void kernel_launch(void* const* d_in, const int* in_sizes, int n_in,
                              void* d_out, int out_size)
{
    const float* inp   = (const float*)d_in[0];
    const float* h0f   = (const float*)d_in[1];
    const float* h0b   = (const float*)d_in[2];
    const float* Wih_f = (const float*)d_in[3];
    const float* Whh_f = (const float*)d_in[4];
    const float* bih_f = (const float*)d_in[5];
    const float* bhh_f = (const float*)d_in[6];
    const float* Wih_b = (const float*)d_in[7];
    const float* Whh_b = (const float*)d_in[8];
    const float* bih_b = (const float*)d_in[9];
    const float* bhh_b = (const float*)d_in[10];
    float* out = (float*)d_out;

    cudaFuncSetAttribute(gru_rec, cudaFuncAttributeMaxDynamicSharedMemorySize, SMEMB);

    init_k<<<128, 256>>>(h0f, h0b);
    dim3 ga(G3 / 64, M_ROWS / 64);
    gemm_in<<<ga, 128>>>(inp, Wih_f, bih_f, 0);
    gemm_in<<<ga, 128>>>(inp, Wih_b, bih_b, 1);
    gru_rec<<<128, 192, SMEMB>>>(Whh_f, Whh_b, bhh_f, bhh_b, out);
}

// round 12
// speedup vs baseline: 1.6239x; 1.6239x over previous
#include <cuda_runtime.h>
#include <math.h>

#define T_STEPS 512
#define B_SZ    64
#define HID     512
#define G3      1536
#define M_ROWS  (T_STEPS * B_SZ)          // 32768
#define OUT_TB  (T_STEPS * B_SZ * 1024)   // 33554432 floats

// ---------------- device scratch (static: no allocations allowed) ----------------
__device__ float    g_gi[2L * M_ROWS * G3];         // [dir][t*B+b][1536]
__device__ float    g_h[2 * 2 * B_SZ * HID];        // [dir][parity][b][h]
__device__ unsigned g_bar2[2];                      // per-direction barrier counters

static __device__ __forceinline__ unsigned ld_acq(const unsigned* p) {
    unsigned v;
    asm volatile("ld.acquire.gpu.u32 %0, [%1];" : "=r"(v) : "l"(p));
    return v;
}

// =====================================================================
// Kernel A: gi[dir][m][n] = inp[m][:] . Wih[n][:] + bih[n]
// M=32768, N=1536, K=512.  BM=BN=64, BK=16, 128 threads, 4x8 thread tile.
// =====================================================================
#define ASTR 68
__global__ void __launch_bounds__(128) gemm_in(
    const float* __restrict__ inp, const float* __restrict__ Wih,
    const float* __restrict__ bih, int dir)
{
    __shared__ float As[16 * ASTR];
    __shared__ float Bs[16 * ASTR];
    const int t  = threadIdx.x;
    const int m0 = blockIdx.y * 64;
    const int n0 = blockIdx.x * 64;
    const float* Ap = inp + (size_t)m0 * 512;
    const float* Bp = Wih + (size_t)n0 * 512;
    const int lr = t >> 2;        // 0..31
    const int lv = t & 3;         // float4 index within 16-k panel
    const int tm = t & 15;        // 16 m-groups of 4
    const int tn = t >> 4;        // 8 n-groups of 8

    float acc[4][8];
#pragma unroll
    for (int i = 0; i < 4; i++)
#pragma unroll
        for (int j = 0; j < 8; j++) acc[i][j] = 0.f;

    for (int k0 = 0; k0 < 512; k0 += 16) {
#pragma unroll
        for (int ps = 0; ps < 2; ps++) {
            int r = lr + ps * 32;
            float4 av = *(const float4*)(Ap + (size_t)r * 512 + k0 + lv * 4);
            float4 wv = *(const float4*)(Bp + (size_t)r * 512 + k0 + lv * 4);
            int kb = lv * 4;
            As[(kb + 0) * ASTR + r] = av.x;  As[(kb + 1) * ASTR + r] = av.y;
            As[(kb + 2) * ASTR + r] = av.z;  As[(kb + 3) * ASTR + r] = av.w;
            Bs[(kb + 0) * ASTR + r] = wv.x;  Bs[(kb + 1) * ASTR + r] = wv.y;
            Bs[(kb + 2) * ASTR + r] = wv.z;  Bs[(kb + 3) * ASTR + r] = wv.w;
        }
        __syncthreads();
#pragma unroll
        for (int kk = 0; kk < 16; kk++) {
            float4 a  = *(const float4*)&As[kk * ASTR + tm * 4];
            float4 w0 = *(const float4*)&Bs[kk * ASTR + tn * 8];
            float4 w1 = *(const float4*)&Bs[kk * ASTR + tn * 8 + 4];
            const float aa[4] = {a.x, a.y, a.z, a.w};
            const float ww[8] = {w0.x, w0.y, w0.z, w0.w, w1.x, w1.y, w1.z, w1.w};
#pragma unroll
            for (int i = 0; i < 4; i++)
#pragma unroll
                for (int j = 0; j < 8; j++) acc[i][j] += aa[i] * ww[j];
        }
        __syncthreads();
    }

    float bj[8];
#pragma unroll
    for (int j = 0; j < 8; j++) bj[j] = bih[n0 + tn * 8 + j];
    float* op = g_gi + (size_t)dir * M_ROWS * G3;
#pragma unroll
    for (int i = 0; i < 4; i++) {
        size_t row = (size_t)(m0 + tm * 4 + i) * G3 + n0 + tn * 8;
        float4 v0 = make_float4(acc[i][0] + bj[0], acc[i][1] + bj[1],
                                acc[i][2] + bj[2], acc[i][3] + bj[3]);
        float4 v1 = make_float4(acc[i][4] + bj[4], acc[i][5] + bj[5],
                                acc[i][6] + bj[6], acc[i][7] + bj[7]);
        *(float4*)(op + row)     = v0;
        *(float4*)(op + row + 4) = v1;
    }
}

// =====================================================================
// Init: reset barriers, load h0 into parity-0 h buffers.
// =====================================================================
__global__ void init_k(const float* __restrict__ h0f, const float* __restrict__ h0b)
{
    int i = blockIdx.x * blockDim.x + threadIdx.x;
    if (i < 2) g_bar2[i] = 0u;
    if (i < B_SZ * HID) {
        g_h[i]         = h0f[i];   // dir0, parity0
        g_h[65536 + i] = h0b[i];   // dir1, parity0
    }
}

// =====================================================================
// Kernel B: persistent bidirectional GRU recurrence.
// 128 blocks: dir = bx/64, each owns 8 h-cols (24 gate rows of Whh in smem,
// loaded once, reused for all 512 steps).
// 384 threads = 4 k-quarters x 96 (16 b-groups x 6 c-groups, 4x4 tiles).
// Full h staged to smem once per step; 3 block syncs + 1 per-direction
// grid barrier (64 arrivals) per step. All 128 blocks resident:
// 221184 B dyn smem -> 1 block/SM, 128 <= 148 SMs.
// smem: ws 512x28 | hs 512x68 | ghs 4x(24x64)
// =====================================================================
#define WSN   (512 * 28)
#define HSN   (512 * 68)
#define GHN   1536
#define SMEMB ((WSN + HSN + 4 * GHN) * 4)

__global__ void __launch_bounds__(384) gru_rec(
    const float* __restrict__ Whh_f, const float* __restrict__ Whh_b,
    const float* __restrict__ bhh_f, const float* __restrict__ bhh_b,
    float* __restrict__ out)
{
    extern __shared__ float sm[];
    float* ws  = sm;            // [k 0..511][c 0..27]
    float* hs  = ws + WSN;      // [k 0..511][b 0..63] stride 68
    float* ghs = hs + HSN;      // 4 quarters of [c 0..23][b 0..63]

    const int bx  = blockIdx.x;
    const int dir = bx >> 6;
    const int j0  = (bx & 63) * 8;
    const int tid = threadIdx.x;
    const int q    = tid / 96;        // k-quarter 0..3
    const int htid = tid % 96;
    const int bg = htid & 15;         // b-group (4 rows)
    const int cg = htid / 16;         // c-group (4 cols), 0..5
    const int kbase = q * 128;

    const float* Whh = dir ? Whh_b : Whh_f;
    const float* bhh = dir ? bhh_b : bhh_f;
    unsigned* bar = &g_bar2[dir];

    // Load this block's 24 Whh rows into smem [k][c], once.
    for (int idx = tid; idx < 24 * 512; idx += 384) {
        int c = idx >> 9, k = idx & 511;
        int gr = (c >> 3) * 512 + j0 + (c & 7);
        ws[k * 28 + c] = Whh[(size_t)gr * 512 + k];
    }
    __syncthreads();

    // Gate-loop index precompute (each thread handles <=2 of 512 outputs).
    int gb_[2], gj_[2], gn_ = 0;
#pragma unroll
    for (int u = 0; u < 2; u++) {
        int idx = tid + u * 384;
        if (idx < 512) { gb_[gn_] = idx >> 3; gj_[gn_] = idx & 7; gn_++; }
    }

    for (int s = 0; s < T_STEPS; s++) {
        const int par = s & 1;
        const float* hp = g_h + ((size_t)dir * 2 + par) * (B_SZ * HID);
        float* hw = g_h + ((size_t)dir * 2 + (1 - par)) * (B_SZ * HID);

        // Prefetch this step's gi gate inputs (ready long before gate math).
        const int tg = dir ? (511 - s) : s;
        const float* gip = g_gi + ((size_t)dir * T_STEPS + tg) * (B_SZ * G3);
        float pir[2], piz[2], pin[2];
#pragma unroll
        for (int u = 0; u < 2; u++) {
            if (u < gn_) {
                const float* gp = gip + (size_t)gb_[u] * G3 + j0 + gj_[u];
                pir[u] = __ldg(gp);
                piz[u] = __ldg(gp + 512);
                pin[u] = __ldg(gp + 1024);
            }
        }

        // Stage the full h (64 x 512) transposed into hs[k][b], stride 68.
        // v layout: bits[0:2)=kv_lo (float4 within 64B run), [2:8)=b, [8:)=kv_hi
        // -> 64B-coalesced GMEM reads, <=2-way smem store conflicts.
#pragma unroll
        for (int w = 0; w < 22; w++) {
            int v = tid + w * 384;
            if (v < 8192) {
                int kv_lo = v & 3;
                int b     = (v >> 2) & 63;
                int kv_hi = v >> 8;
                int kv = kv_hi * 4 + kv_lo;                 // 0..127 float4 index
                float4 x = *(const float4*)(hp + (size_t)b * 512 + kv * 4);
                int ib = kv * 4;
                hs[(ib + 0) * 68 + b] = x.x;  hs[(ib + 1) * 68 + b] = x.y;
                hs[(ib + 2) * 68 + b] = x.z;  hs[(ib + 3) * 68 + b] = x.w;
            }
        }
        __syncthreads();

        // GEMM quarter: acc[4][4] over 128 k-values, 16 FMA + 2 LDS.128 per k.
        float acc[4][4];
#pragma unroll
        for (int i = 0; i < 4; i++)
#pragma unroll
            for (int j = 0; j < 4; j++) acc[i][j] = 0.f;

#pragma unroll 8
        for (int kk = 0; kk < 128; kk++) {
            float4 h4 = *(const float4*)&hs[(kbase + kk) * 68 + bg * 4];
            float4 w4 = *(const float4*)&ws[(kbase + kk) * 28 + cg * 4];
            const float hh[4] = {h4.x, h4.y, h4.z, h4.w};
            const float wc[4] = {w4.x, w4.y, w4.z, w4.w};
#pragma unroll
            for (int i = 0; i < 4; i++)
#pragma unroll
                for (int j = 0; j < 4; j++) acc[i][j] += hh[i] * wc[j];
        }

        // Store partials for this quarter.
        float* ghp = ghs + q * GHN;
#pragma unroll
        for (int j = 0; j < 4; j++)
#pragma unroll
            for (int i = 0; i < 4; i++)
                ghp[(cg * 4 + j) * 64 + bg * 4 + i] = acc[i][j];
        __syncthreads();

        // Gate math for this block's 8 h-columns (512 outputs).
#pragma unroll
        for (int u = 0; u < 2; u++) {
            if (u < gn_) {
                int b = gb_[u], jj = gj_[u];
                int j = j0 + jj;
                float gr = bhh[j], gz = bhh[512 + j], gn = bhh[1024 + j];
#pragma unroll
                for (int qq = 0; qq < 4; qq++) {
                    const float* gq = ghs + qq * GHN;
                    gr += gq[jj * 64 + b];
                    gz += gq[(8 + jj) * 64 + b];
                    gn += gq[(16 + jj) * 64 + b];
                }
                float r = 1.f / (1.f + __expf(-(pir[u] + gr)));
                float z = 1.f / (1.f + __expf(-(piz[u] + gz)));
                float n = tanhf(pin[u] + r * gn);
                float hn = (1.f - z) * n + z * hp[(size_t)b * 512 + j];
                hw[(size_t)b * 512 + j] = hn;
                out[(size_t)tg * 65536 + (size_t)b * 1024 + dir * 512 + j] = hn;
                if (s == 511)
                    out[(size_t)OUT_TB + dir * 32768 + b * 512 + j] = hn;
            }
        }

        // Per-direction grid barrier (monotonic; 64 resident blocks/dir).
        __threadfence();
        __syncthreads();
        if (tid == 0) {
            atomicAdd(bar, 1u);
            unsigned target = (unsigned)(s + 1) * 64u;
            while (ld_acq(bar) < target) __nanosleep(64);
        }
        __syncthreads();
    }
}

// =====================================================================
extern "C" void kernel_launch(void* const* d_in, const int* in_sizes, int n_in,
                              void* d_out, int out_size)
{
    const float* inp   = (const float*)d_in[0];
    const float* h0f   = (const float*)d_in[1];
    const float* h0b   = (const float*)d_in[2];
    const float* Wih_f = (const float*)d_in[3];
    const float* Whh_f = (const float*)d_in[4];
    const float* bih_f = (const float*)d_in[5];
    const float* bhh_f = (const float*)d_in[6];
    const float* Wih_b = (const float*)d_in[7];
    const float* Whh_b = (const float*)d_in[8];
    const float* bih_b = (const float*)d_in[9];
    const float* bhh_b = (const float*)d_in[10];
    float* out = (float*)d_out;

    cudaFuncSetAttribute(gru_rec, cudaFuncAttributeMaxDynamicSharedMemorySize, SMEMB);

    init_k<<<128, 256>>>(h0f, h0b);
    dim3 ga(G3 / 64, M_ROWS / 64);
    gemm_in<<<ga, 128>>>(inp, Wih_f, bih_f, 0);
    gemm_in<<<ga, 128>>>(inp, Wih_b, bih_b, 1);
    gru_rec<<<128, 384, SMEMB>>>(Whh_f, Whh_b, bhh_f, bhh_b, out);
}